// round 17
// baseline (speedup 1.0000x reference)
#include <cuda_runtime.h>

#define BQ 4096
#define TT 200
#define DD 64
#define HH 64

// ---------------- scratch (static device globals: allocation-free) ----------
__device__ int g_hist[256];
__device__ int g_cursor[256];
__device__ int g_perm[BQ];
__device__ float g_projG[(size_t)BQ * TT * 128];   // gate x-projection (+bias)
__device__ float g_projC[(size_t)BQ * TT * 64];    // cand x-projection (+bias)

// ---------------- counting sort of rows by seq_len (ascending) --------------
__global__ void k_hist_init() { g_hist[threadIdx.x] = 0; }

__global__ void k_hist(const int* __restrict__ sl) {
    int i = blockIdx.x * blockDim.x + threadIdx.x;
    if (i < BQ) atomicAdd(&g_hist[sl[i] & 255], 1);
}

__global__ void k_scan() {
    if (threadIdx.x == 0) {
        int s = 0;
        for (int i = 0; i < 256; i++) { int c = g_hist[i]; g_cursor[i] = s; s += c; }
    }
}

__global__ void k_scatter(const int* __restrict__ sl) {
    int i = blockIdx.x * blockDim.x + threadIdx.x;
    if (i < BQ) {
        int pos = atomicAdd(&g_cursor[sl[i] & 255], 1);
        g_perm[pos] = i;
    }
}

// ---------------- math helpers ----------------------------------------------
__device__ __forceinline__ float sigf(float v) {
    return __fdividef(1.f, 1.f + __expf(-v));
}
__device__ __forceinline__ float tanhe(float v) {
    return 1.f - __fdividef(2.f, __expf(2.f * v) + 1.f);
}
__device__ __forceinline__ void ffma2(unsigned long long& d,
                                      unsigned long long a, unsigned long long b) {
    asm("fma.rn.f32x2 %0, %1, %2, %0;" : "+l"(d) : "l"(a), "l"(b));
}
__device__ __forceinline__ unsigned long long pack2(float lo, float hi) {
    unsigned long long u;
    asm("mov.b64 %0, {%1,%2};" : "=l"(u) : "f"(lo), "f"(hi));
    return u;
}
__device__ __forceinline__ float pairsum(unsigned long long u) {
    float lo, hi;
    asm("mov.b64 {%0,%1}, %2;" : "=f"(lo), "=f"(hi) : "l"(u));
    return lo + hi;
}
__device__ __forceinline__ ulonglong2 ld128(const float* p) {
    return *reinterpret_cast<const ulonglong2*>(p);
}

// ---------------- phase 1: x-projections ------------------------------------
// Register-blocked skinny GEMM: for each (b, t<L) item compute
//   G[bt, 0:128] = x[bt,:] @ Wg[0:64,:] + bg
//   C[bt, 0:64]  = x[bt,:] @ Wc[0:64,:] + bc
// One warp handles 8 timesteps of one row; weights j-major in SMEM (stride 68,
// odd in 16B units -> conflict-free LDS.128); x read via uniform LDG.128.
__global__ void __launch_bounds__(256, 1)
augru_proj(const float* __restrict__ x, const int* __restrict__ sl,
           const float* __restrict__ Wg, const float* __restrict__ bg,
           const float* __restrict__ Wc, const float* __restrict__ bc)
{
    extern __shared__ float sm[];                  // 192*68 floats
    const int tid = threadIdx.x;
    for (int i = tid; i < 192 * 64; i += 256) {
        int j = i >> 6, k = i & 63;
        sm[j * 68 + k] = (j < 128) ? Wg[k * 128 + j] : Wc[k * 64 + (j - 128)];
    }
    __syncthreads();

    const int lane = tid & 31;
    const int gw = blockIdx.x * 8 + (tid >> 5);    // global warp id, 0..1183
    const float* w0 = sm + lane * 68;
    const float* w1 = sm + (lane + 32) * 68;
    const float* w2 = sm + (lane + 64) * 68;
    const float* w3 = sm + (lane + 96) * 68;
    const float* w4 = sm + (lane + 128) * 68;
    const float* w5 = sm + (lane + 160) * 68;
    const float b0 = bg[lane], b1 = bg[lane + 32];
    const float b2 = bg[lane + 64], b3 = bg[lane + 96];
    const float b4 = bc[lane], b5 = bc[lane + 32];

    for (int c = gw; c < BQ * 25; c += 148 * 8) {  // 25 chunks of 8 t per row
        const int b = c / 25;
        const int t0 = (c % 25) * 8;
        if (t0 >= sl[b]) continue;
        const float* xb = x + ((size_t)b * TT + t0) * DD;

        unsigned long long a0[8], a1[8], a2[8], a3[8], a4[8], a5[8];
        #pragma unroll
        for (int tt = 0; tt < 8; tt++) {
            a0[tt] = 0ull; a1[tt] = 0ull; a2[tt] = 0ull;
            a3[tt] = 0ull; a4[tt] = 0ull; a5[tt] = 0ull;
        }
        #pragma unroll 2
        for (int k4 = 0; k4 < 64; k4 += 4) {
            const ulonglong2 W0 = ld128(w0 + k4);
            const ulonglong2 W1 = ld128(w1 + k4);
            const ulonglong2 W2 = ld128(w2 + k4);
            const ulonglong2 W3 = ld128(w3 + k4);
            const ulonglong2 W4 = ld128(w4 + k4);
            const ulonglong2 W5 = ld128(w5 + k4);
            #pragma unroll
            for (int tt = 0; tt < 8; tt++) {
                const ulonglong2 xv = ld128(xb + tt * DD + k4);
                ffma2(a0[tt], W0.x, xv.x); ffma2(a0[tt], W0.y, xv.y);
                ffma2(a1[tt], W1.x, xv.x); ffma2(a1[tt], W1.y, xv.y);
                ffma2(a2[tt], W2.x, xv.x); ffma2(a2[tt], W2.y, xv.y);
                ffma2(a3[tt], W3.x, xv.x); ffma2(a3[tt], W3.y, xv.y);
                ffma2(a4[tt], W4.x, xv.x); ffma2(a4[tt], W4.y, xv.y);
                ffma2(a5[tt], W5.x, xv.x); ffma2(a5[tt], W5.y, xv.y);
            }
        }
        #pragma unroll
        for (int tt = 0; tt < 8; tt++) {
            const size_t bt = (size_t)b * TT + t0 + tt;
            float* G = g_projG + bt * 128;
            float* C = g_projC + bt * 64;
            G[lane]      = b0 + pairsum(a0[tt]);
            G[lane + 32] = b1 + pairsum(a1[tt]);
            G[lane + 64] = b2 + pairsum(a2[tt]);
            G[lane + 96] = b3 + pairsum(a3[tt]);
            C[lane]      = b4 + pairsum(a4[tt]);
            C[lane + 32] = b5 + pairsum(a5[tt]);
        }
    }
}

// ---------------- phase 2: recurrence (h-part only) --------------------------
// NR=4 rows/warp, complementary LPT pairing (as R16). Inputs h / r*h broadcast
// via __shfl_sync (no staging SMEM, no syncwarp). Only weight LDS hit the
// crossbar: 96 LDS.128 per warp-step.
__global__ void __launch_bounds__(256, 1)
augru_rec(const int* __restrict__ sl, const float* __restrict__ att,
          const float* __restrict__ Wg, const float* __restrict__ Wc,
          float* __restrict__ out)
{
    extern __shared__ float sm[];
    float* sWgh = sm;                              // 128*68
    float* sWch = sm + 128 * 68;                   // 64*68

    const int tid = threadIdx.x;
    for (int i = tid; i < 128 * 64; i += 256) {
        int j = i >> 6, k = i & 63;
        sWgh[j * 68 + k] = Wg[(64 + k) * 128 + j]; // h-part rows of W_gate
    }
    for (int i = tid; i < 64 * 64; i += 256) {
        int j = i >> 6, k = i & 63;
        sWch[j * 68 + k] = Wc[(64 + k) * 64 + j];  // h-part rows of W_cand
    }
    __syncthreads();

    const int lane = tid & 31;
    const int widx = tid >> 5;
    const int sG = blockIdx.x * 4 + (widx & 3);    // SMSP id, 0..591
    int p;
    if (widx < 4) p = sG;
    else          p = (sG < 432) ? (1023 - sG) : -1;
    if (p < 0) return;

    const float* wg0 = sWgh + lane * 68;
    const float* wg1 = sWgh + (lane + 32) * 68;
    const float* wg2 = sWgh + (lane + 64) * 68;
    const float* wg3 = sWgh + (lane + 96) * 68;
    const float* wc0 = sWch + lane * 68;
    const float* wc1 = sWch + (lane + 32) * 68;

    int L[4];
    const float* ab[4]; float* ob[4];
    const float* gp[4]; const float* cp[4];
    #pragma unroll
    for (int r = 0; r < 4; r++) {
        int row = g_perm[4095 - 4 * p - r];        // descending-L groups
        L[r] = sl[row];
        ab[r] = att + (size_t)row * TT;
        ob[r] = out + (size_t)row * TT * HH;
        gp[r] = g_projG + (size_t)row * TT * 128;
        cp[r] = g_projC + (size_t)row * TT * 64;
    }
    const int Lmax = L[0];

    float h0a[4] = {0.f, 0.f, 0.f, 0.f}, h1a[4] = {0.f, 0.f, 0.f, 0.f};

    float pg0[4], pg1[4], pg2[4], pg3[4], pc0[4], pc1[4], pa[4];
    if (Lmax > 0) {
        #pragma unroll
        for (int r = 0; r < 4; r++) {
            pg0[r] = gp[r][lane];      pg1[r] = gp[r][lane + 32];
            pg2[r] = gp[r][lane + 64]; pg3[r] = gp[r][lane + 96];
            pc0[r] = cp[r][lane];      pc1[r] = cp[r][lane + 32];
            pa[r]  = ab[r][0];
        }
    }

    for (int t = 0; t < Lmax; t++) {
        unsigned long long ag0[4], ag1[4], ag2[4], ag3[4], ac0[4], ac1[4];
        float at_s[4];
        #pragma unroll
        for (int r = 0; r < 4; r++) {
            ag0[r] = pack2(pg0[r], 0.f); ag1[r] = pack2(pg1[r], 0.f);
            ag2[r] = pack2(pg2[r], 0.f); ag3[r] = pack2(pg3[r], 0.f);
            ac0[r] = pack2(pc0[r], 0.f); ac1[r] = pack2(pc1[r], 0.f);
            at_s[r] = pa[r];
        }
        // prefetch next-step projections / attention
        if (t + 1 < Lmax) {
            const int tn = t + 1;
            #pragma unroll
            for (int r = 0; r < 4; r++) {
                const float* g = gp[r] + tn * 128;
                const float* c = cp[r] + tn * 64;
                pg0[r] = g[lane];      pg1[r] = g[lane + 32];
                pg2[r] = g[lane + 64]; pg3[r] = g[lane + 96];
                pc0[r] = c[lane];      pc1[r] = c[lane + 32];
                pa[r]  = ab[r][tn];
            }
        }

        // ---- gate h-matvec: h(64) @ Wg_h(64x128), v via shuffle ----
        #pragma unroll 4
        for (int k4 = 0; k4 < 32; k4 += 4) {
            const ulonglong2 W0 = ld128(wg0 + k4);
            const ulonglong2 W1 = ld128(wg1 + k4);
            const ulonglong2 W2 = ld128(wg2 + k4);
            const ulonglong2 W3 = ld128(wg3 + k4);
            #pragma unroll
            for (int r = 0; r < 4; r++) {
                float s0 = __shfl_sync(0xffffffffu, h0a[r], k4);
                float s1 = __shfl_sync(0xffffffffu, h0a[r], k4 + 1);
                float s2 = __shfl_sync(0xffffffffu, h0a[r], k4 + 2);
                float s3 = __shfl_sync(0xffffffffu, h0a[r], k4 + 3);
                const unsigned long long vx = pack2(s0, s1);
                const unsigned long long vy = pack2(s2, s3);
                ffma2(ag0[r], W0.x, vx); ffma2(ag0[r], W0.y, vy);
                ffma2(ag1[r], W1.x, vx); ffma2(ag1[r], W1.y, vy);
                ffma2(ag2[r], W2.x, vx); ffma2(ag2[r], W2.y, vy);
                ffma2(ag3[r], W3.x, vx); ffma2(ag3[r], W3.y, vy);
            }
        }
        #pragma unroll 4
        for (int k4 = 32; k4 < 64; k4 += 4) {
            const ulonglong2 W0 = ld128(wg0 + k4);
            const ulonglong2 W1 = ld128(wg1 + k4);
            const ulonglong2 W2 = ld128(wg2 + k4);
            const ulonglong2 W3 = ld128(wg3 + k4);
            #pragma unroll
            for (int r = 0; r < 4; r++) {
                float s0 = __shfl_sync(0xffffffffu, h1a[r], k4 - 32);
                float s1 = __shfl_sync(0xffffffffu, h1a[r], k4 - 31);
                float s2 = __shfl_sync(0xffffffffu, h1a[r], k4 - 30);
                float s3 = __shfl_sync(0xffffffffu, h1a[r], k4 - 29);
                const unsigned long long vx = pack2(s0, s1);
                const unsigned long long vy = pack2(s2, s3);
                ffma2(ag0[r], W0.x, vx); ffma2(ag0[r], W0.y, vy);
                ffma2(ag1[r], W1.x, vx); ffma2(ag1[r], W1.y, vy);
                ffma2(ag2[r], W2.x, vx); ffma2(ag2[r], W2.y, vy);
                ffma2(ag3[r], W3.x, vx); ffma2(ag3[r], W3.y, vy);
            }
        }

        float rh0[4], rh1[4], u0[4], u1[4];
        #pragma unroll
        for (int r = 0; r < 4; r++) {
            const float rg0 = sigf(pairsum(ag0[r]));
            const float rg1 = sigf(pairsum(ag1[r]));
            u0[r] = sigf(pairsum(ag2[r]));
            u1[r] = sigf(pairsum(ag3[r]));
            rh0[r] = rg0 * h0a[r];
            rh1[r] = rg1 * h1a[r];
        }

        // ---- candidate h-matvec: (r*h)(64) @ Wc_h(64x64), v via shuffle ----
        #pragma unroll 4
        for (int k4 = 0; k4 < 32; k4 += 4) {
            const ulonglong2 W0 = ld128(wc0 + k4);
            const ulonglong2 W1 = ld128(wc1 + k4);
            #pragma unroll
            for (int r = 0; r < 4; r++) {
                float s0 = __shfl_sync(0xffffffffu, rh0[r], k4);
                float s1 = __shfl_sync(0xffffffffu, rh0[r], k4 + 1);
                float s2 = __shfl_sync(0xffffffffu, rh0[r], k4 + 2);
                float s3 = __shfl_sync(0xffffffffu, rh0[r], k4 + 3);
                const unsigned long long vx = pack2(s0, s1);
                const unsigned long long vy = pack2(s2, s3);
                ffma2(ac0[r], W0.x, vx); ffma2(ac0[r], W0.y, vy);
                ffma2(ac1[r], W1.x, vx); ffma2(ac1[r], W1.y, vy);
            }
        }
        #pragma unroll 4
        for (int k4 = 32; k4 < 64; k4 += 4) {
            const ulonglong2 W0 = ld128(wc0 + k4);
            const ulonglong2 W1 = ld128(wc1 + k4);
            #pragma unroll
            for (int r = 0; r < 4; r++) {
                float s0 = __shfl_sync(0xffffffffu, rh1[r], k4 - 32);
                float s1 = __shfl_sync(0xffffffffu, rh1[r], k4 - 31);
                float s2 = __shfl_sync(0xffffffffu, rh1[r], k4 - 30);
                float s3 = __shfl_sync(0xffffffffu, rh1[r], k4 - 29);
                const unsigned long long vx = pack2(s0, s1);
                const unsigned long long vy = pack2(s2, s3);
                ffma2(ac0[r], W0.x, vx); ffma2(ac0[r], W0.y, vy);
                ffma2(ac1[r], W1.x, vx); ffma2(ac1[r], W1.y, vy);
            }
        }

        #pragma unroll
        for (int r = 0; r < 4; r++) {
            const float ct0 = tanhe(pairsum(ac0[r]));
            const float ct1 = tanhe(pairsum(ac1[r]));
            const float uu0 = (1.f - at_s[r]) * u0[r];
            const float uu1 = (1.f - at_s[r]) * u1[r];
            h0a[r] = uu0 * h0a[r] + (1.f - uu0) * ct0;
            h1a[r] = uu1 * h1a[r] + (1.f - uu1) * ct1;
            if (t < L[r]) {
                float* op = ob[r] + t * HH;
                op[lane] = h0a[r]; op[lane + 32] = h1a[r];
            }
        }
    }

    // zero-fill masked tails (output poisoned by harness)
    #pragma unroll
    for (int r = 0; r < 4; r++) {
        float* op = ob[r] + L[r] * HH;
        for (int t = L[r]; t < TT; t++) {
            op[lane] = 0.f; op[lane + 32] = 0.f;
            op += HH;
        }
    }
}

// ---------------- launch -----------------------------------------------------
extern "C" void kernel_launch(void* const* d_in, const int* in_sizes, int n_in,
                              void* d_out, int out_size)
{
    const float* x  = (const float*)d_in[0];   // rnn_input  [B,T,64]
    const int*   sl = (const int*)d_in[1];     // sequence_length [B,1]
    const float* at = (const float*)d_in[2];   // att_score  [B,T,1]
    const float* Wg = (const float*)d_in[3];   // [128,128]
    const float* bg = (const float*)d_in[4];   // [128]
    const float* Wc = (const float*)d_in[5];   // [128,64]
    const float* bc = (const float*)d_in[6];   // [64]
    float* out = (float*)d_out;                // [B,T,64]

    const int smem_proj = 192 * 68 * 4;        // 52224
    const int smem_rec  = (128 * 68 + 64 * 68) * 4; // 52224
    cudaFuncSetAttribute(augru_proj, cudaFuncAttributeMaxDynamicSharedMemorySize,
                         smem_proj);
    cudaFuncSetAttribute(augru_rec, cudaFuncAttributeMaxDynamicSharedMemorySize,
                         smem_rec);

    k_hist_init<<<1, 256>>>();
    k_hist<<<(BQ + 255) / 256, 256>>>(sl);
    k_scan<<<1, 32>>>();
    k_scatter<<<(BQ + 255) / 256, 256>>>(sl);
    augru_proj<<<148, 256, smem_proj>>>(x, sl, Wg, bg, Wc, bc);
    augru_rec<<<148, 256, smem_rec>>>(sl, at, Wg, Wc, out);
}